// round 8
// baseline (speedup 1.0000x reference)
#include <cuda_runtime.h>

#define BB 256      // batch
#define NN 2048     // nodes
#define UU 128      // node_units
#define GG 256      // graph_units
#define RCH 128     // partial row-chunks (16 adj rows each)
#define NC4 (NN/4)  // 512 float4 columns
#define NPREP 4     // blocks doing w-fold slices (32 u each)

// Scratch (device globals; counters self-reset every launch)
__device__ float4 g_part4[RCH * NC4];    // partial column sums (1 MB)
__device__ float4 g_c4[NC4];             // column means of adj
__device__ float  g_ApP[NPREP][GG];      // partial sum_{u:w1>0} w1[u]*w2[u,g]
__device__ float  g_AmP[NPREP][GG];      // partial sum_{u:w1<0} w1[u]*w2[u,g]
__device__ int    g_b1nz;                // 1 iff any b1[u] != 0
__device__ int    g_ctr1;                // colsum-writer arrivals   (zero-init)
__device__ int    g_ctr2;                // reducer+prep arrivals    (zero-init)
__device__ int    g_ctr3;                // exit arrivals -> reset   (zero-init)

// ---------------------------------------------------------------------------
// Single persistent kernel. grid(256), block(256), all blocks co-resident.
//   Every block   : prefetch its nf row, then colsum partial (16 rows x 1 KB).
//   Blocks 0..7   : after ctr1==256, reduce partials -> column means (256 cols).
//   Blocks 8..11  : fold a 32-u slice of w1 through w2 (overlaps the drain).
//   Every block   : after ctr2==12, compute P/M for its batch + output row.
// ---------------------------------------------------------------------------
__global__ void __launch_bounds__(256, 2)
mono(const float4* __restrict__ nf4,
     const float4* __restrict__ adj4,
     const float*  __restrict__ w1,
     const float*  __restrict__ b1,
     const float*  __restrict__ w2,
     const float*  __restrict__ b2,
     float*        __restrict__ out) {
    const int bid = blockIdx.x;
    const int tid = threadIdx.x;

    // ---- Step A: prefetch this block's nf row (latency hides under colsum)
    const float4 v0 = nf4[(size_t)bid * NC4 + tid];
    const float4 v1 = nf4[(size_t)bid * NC4 + 256 + tid];

    // ---- Step B: colsum partial (16 rows x 256 f4-cols, MLP-16)
    const int c4 = (bid & 1) * 256 + tid;
    const int r0 = (bid >> 1) * 16;
    float4 a[16];
#pragma unroll
    for (int i = 0; i < 16; i++)
        a[i] = adj4[(size_t)(r0 + i) * NC4 + c4];
    float4 acc = a[0];
#pragma unroll
    for (int i = 1; i < 16; i++) {
        acc.x += a[i].x; acc.y += a[i].y; acc.z += a[i].z; acc.w += a[i].w;
    }
    g_part4[(size_t)(bid >> 1) * NC4 + c4] = acc;

    __threadfence();
    __syncthreads();
    if (tid == 0) atomicAdd(&g_ctr1, 1);

    if (bid < 8) {
        // ---- reducer: wait for all writers, reduce a 256-column slice
        if (tid == 0) {
            while (*(volatile int*)&g_ctr1 < 256) { __nanosleep(32); }
        }
        __syncthreads();
        __threadfence();

        const int j = bid * 256 + tid;
        const float* part = (const float*)g_part4;
        float s = 0.f;
#pragma unroll 16
        for (int y = 0; y < RCH; y++) s += part[(size_t)y * NN + j];
        ((float*)g_c4)[j] = s * (1.0f / (float)NN);

        __threadfence();
        __syncthreads();
        if (tid == 0) atomicAdd(&g_ctr2, 1);
    } else if (bid < 8 + NPREP) {
        // ---- prep: fold a 32-u slice of w1 through w2 (overlaps drain)
        const int k  = bid - 8;
        const int u0 = k * 32;
        float ap = 0.f, am = 0.f;
#pragma unroll 8
        for (int u = 0; u < 32; u++) {
            const float w = w1[u0 + u];
            const float x = w2[(u0 + u) * GG + tid];
            if (w > 0.f) ap = fmaf(w, x, ap);
            else         am = fmaf(w, x, am);
        }
        g_ApP[k][tid] = ap;
        g_AmP[k][tid] = am;
        if (k == 0) {
            int nz = (tid < UU && b1[tid] != 0.f) ? 1 : 0;
            nz = __syncthreads_or(nz);
            if (tid == 0) g_b1nz = nz;
        }
        __threadfence();
        __syncthreads();
        if (tid == 0) atomicAdd(&g_ctr2, 1);
    }

    // ---- barrier: wait for column means + folded weights
    if (tid == 0) {
        while (*(volatile int*)&g_ctr2 < 8 + NPREP) { __nanosleep(32); }
    }
    __syncthreads();
    __threadfence();

    // ---- Step D: P/M for this batch from prefetched registers + L2-hot c
    const float4 c0 = g_c4[tid];
    const float4 c1 = g_c4[256 + tid];
    float p = 0.f, m = 0.f;
    p = fmaf(c0.x, fmaxf(v0.x, 0.f), p);  m = fmaf(c0.x, fminf(v0.x, 0.f), m);
    p = fmaf(c0.y, fmaxf(v0.y, 0.f), p);  m = fmaf(c0.y, fminf(v0.y, 0.f), m);
    p = fmaf(c0.z, fmaxf(v0.z, 0.f), p);  m = fmaf(c0.z, fminf(v0.z, 0.f), m);
    p = fmaf(c0.w, fmaxf(v0.w, 0.f), p);  m = fmaf(c0.w, fminf(v0.w, 0.f), m);
    p = fmaf(c1.x, fmaxf(v1.x, 0.f), p);  m = fmaf(c1.x, fminf(v1.x, 0.f), m);
    p = fmaf(c1.y, fmaxf(v1.y, 0.f), p);  m = fmaf(c1.y, fminf(v1.y, 0.f), m);
    p = fmaf(c1.z, fmaxf(v1.z, 0.f), p);  m = fmaf(c1.z, fminf(v1.z, 0.f), m);
    p = fmaf(c1.w, fmaxf(v1.w, 0.f), p);  m = fmaf(c1.w, fminf(v1.w, 0.f), m);

#pragma unroll
    for (int o = 16; o > 0; o >>= 1) {
        p += __shfl_xor_sync(0xFFFFFFFFu, p, o);
        m += __shfl_xor_sync(0xFFFFFFFFu, m, o);
    }
    __shared__ float sp[8], sm_[8];
    const int w = tid >> 5;
    if ((tid & 31) == 0) { sp[w] = p; sm_[w] = m; }
    __syncthreads();
    float P = 0.f, M = 0.f;
#pragma unroll
    for (int i = 0; i < 8; i++) { P += sp[i]; M += sm_[i]; }

    if (!g_b1nz) {
        float ap = 0.f, am = 0.f;
#pragma unroll
        for (int k = 0; k < NPREP; k++) { ap += g_ApP[k][tid]; am += g_AmP[k][tid]; }
        const float o = fmaf(P, ap, fmaf(M, am, b2[tid]));
        out[(size_t)bid * GG + tid] = fmaxf(o, 0.f);
    } else {
        // General path (b1 != 0): exact z[b,u] + small matmul. Never taken for
        // this dataset (b1 == 0); kept for correctness generality.
        __shared__ float zs[UU];
        if (tid < UU) {
            const float ww = w1[tid];
            const float bb = b1[tid];
            const float* row = (const float*)(nf4 + (size_t)bid * NC4);
            const float* c   = (const float*)g_c4;
            float z = 0.f;
            for (int j = 0; j < NN; j++)
                z = fmaf(c[j], fmaxf(fmaf(row[j], ww, bb), 0.f), z);
            zs[tid] = z;
        }
        __syncthreads();
        float o = b2[tid];
#pragma unroll 4
        for (int u = 0; u < UU; u++) o = fmaf(zs[u], w2[u * GG + tid], o);
        out[(size_t)bid * GG + tid] = fmaxf(o, 0.f);
    }

    // ---- counter reset: last block out resets all barrier state
    __syncthreads();
    if (tid == 0) {
        const int d = atomicAdd(&g_ctr3, 1);
        if (d == 255) {
            g_ctr1 = 0;
            g_ctr2 = 0;
            g_ctr3 = 0;
            __threadfence();
        }
    }
}

// ---------------------------------------------------------------------------
extern "C" void kernel_launch(void* const* d_in, const int* in_sizes, int n_in,
                              void* d_out, int out_size) {
    const float* nf  = (const float*)d_in[0];   // (B, N)
    const float* adj = (const float*)d_in[1];   // (N, N)
    const float* w1  = (const float*)d_in[2];   // (1, U)
    const float* b1  = (const float*)d_in[3];   // (U,)
    const float* w2  = (const float*)d_in[4];   // (U, G)
    const float* b2  = (const float*)d_in[5];   // (G,)
    float* out = (float*)d_out;                 // (B, G)

    mono<<<256, 256>>>((const float4*)nf, (const float4*)adj,
                       w1, b1, w2, b2, out);
}